// round 15
// baseline (speedup 1.0000x reference)
#include <cuda_runtime.h>
#include <cuda_fp16.h>
#include <math.h>
#include <stdint.h>

// ---------------- problem constants ----------------
#define BATCH   8192
#define D_IN    128
#define D_COND  3
#define HID     1024
#define NLAY    4
#define NQ      8
#define KCB     1024
#define H3      (3*HID)        // 3072
#define DECK    (HID + D_IN)   // 1152
#define LPN     512
#define DPAD    192            // padded K for fused layer-0 input GEMM
#define INV_TAU (1.0f/0.6f)

// ---------------- scratch (no allocation allowed) ----------------
__device__ float  g_cum  [(size_t)BATCH * D_IN];
__device__ float  g_beff [H3];                        // fused layer-0 bias
__device__ float  g_zerof[1024];                      // stays 0 (never written)
// fp16 buffers
__device__ __half g_gi   [(size_t)BATCH * H3];
__device__ __half g_gh   [(size_t)NLAY * BATCH * H3];
__device__ __half g_xl_h [(size_t)BATCH * HID];
__device__ __half g_hid_h[(size_t)NLAY * BATCH * HID];
__device__ __half g_wih_h[(size_t)NLAY * H3 * HID];
__device__ __half g_whh_h[(size_t)NLAY * H3 * HID];
__device__ __half g_dw_h [(size_t)NQ * KCB * DECK];
__device__ __half g_ET_h [(size_t)NQ * D_IN * KCB];
__device__ __half g_dec_h[(size_t)BATCH * DECK];      // [h | cum]
__device__ __half g_Wfull[(size_t)H3 * DPAD];         // fused layer-0 weight (cols 131..191 stay 0)
__device__ __half g_latwT[(size_t)D_IN * LPN];        // lat_w transposed fp16
__device__ __half g_xpad [(size_t)BATCH * DPAD];      // padded fp16 x

// =====================================================================
__device__ __forceinline__ uint32_t smem_u32(const void* p) {
    uint32_t a;
    asm("{ .reg .u64 t; cvta.to.shared.u64 t, %1; cvt.u32.u64 %0, t; }" : "=r"(a) : "l"(p));
    return a;
}
#define CP_ASYNC16(dst, src) \
    asm volatile("cp.async.cg.shared.global [%0], [%1], 16;" :: "r"(dst), "l"(src) : "memory")
#define CP_COMMIT() asm volatile("cp.async.commit_group;" ::: "memory")
template <int N> __device__ __forceinline__ void cp_wait() {
    asm volatile("cp.async.wait_group %0;" :: "n"(N) : "memory");
}
#define LDSM_X4(r, addr) \
    asm volatile("ldmatrix.sync.aligned.m8n8.x4.shared.b16 {%0,%1,%2,%3}, [%4];" \
        : "=r"((r)[0]), "=r"((r)[1]), "=r"((r)[2]), "=r"((r)[3]) : "r"(addr))
#define LDSM_X2(r, addr) \
    asm volatile("ldmatrix.sync.aligned.m8n8.x2.shared.b16 {%0,%1}, [%2];" \
        : "=r"((r)[0]), "=r"((r)[1]) : "r"(addr))

__device__ __forceinline__ void mma_f16(float* c, const uint32_t* a, const uint32_t* b) {
    asm volatile(
        "mma.sync.aligned.m16n8k16.row.col.f32.f16.f16.f32 "
        "{%0,%1,%2,%3}, {%4,%5,%6,%7}, {%8,%9}, {%0,%1,%2,%3};"
        : "+f"(c[0]), "+f"(c[1]), "+f"(c[2]), "+f"(c[3])
        : "r"(a[0]), "r"(a[1]), "r"(a[2]), "r"(a[3]), "r"(b[0]), "r"(b[1]));
}

// =====================================================================
// fp16 mma.sync GEMM (z-batched): C[M,N] = A[M,K] @ W[N,K]^T + bias[N]
//   (ACC=true: C += A@W^T + bias, fp32 C only)
//   BM=BN=128, BK=64, 256 threads (8 warps: 2m x 4n), warp tile 64x32.
//   3-stage cp.async pipeline; EVERY iteration commits a group (empty in
//   the tail) so wait_group<1> at iteration kt proves stage kt landed.
//   Requires K%64==0, nK>=2, M%128==0, N%128==0, lda/ldw %8==0.
// =====================================================================
#define SPH 72                              // halves per smem row (64 + 8 pad)

template <typename OutT, bool ACC>
__global__ void __launch_bounds__(256, 2)
hgemm(const __half* __restrict__ A, int lda, size_t zsA,
      const __half* __restrict__ W, int ldw, size_t zsW,
      const float* __restrict__ bias, size_t zsB,
      OutT* __restrict__ C, int ldc, size_t zsC, int K)
{
    constexpr int ASTG = 128 * SPH;
    constexpr int STG  = 2 * ASTG;

    extern __shared__ __half smh[];         // [3][STG]

    A    += (size_t)blockIdx.z * zsA;
    W    += (size_t)blockIdx.z * zsW;
    bias += (size_t)blockIdx.z * zsB;
    C    += (size_t)blockIdx.z * zsC;

    const int tid = threadIdx.x, lane = tid & 31, wid = tid >> 5;
    const int bm = blockIdx.y * 128, bn = blockIdx.x * 128;
    const int wm = (wid >> 2) * 64, wn = (wid & 3) * 32;
    const uint32_t sBase = smem_u32(smh);

    float acc[4][4][4];
#pragma unroll
    for (int i = 0; i < 4; i++)
#pragma unroll
        for (int j = 0; j < 4; j++)
#pragma unroll
            for (int k = 0; k < 4; k++) acc[i][j][k] = 0.f;

    const int nK = K / 64;

    auto prefetch = [&](int kt) {
        const int s = kt % 3;
#pragma unroll
        for (int i = 0; i < 4; i++) {
            int c = tid + i * 256;
            int row = c >> 3, q = c & 7;
            uint32_t dst = sBase + (s * STG + row * SPH) * 2 + q * 16;
            CP_ASYNC16(dst, A + (size_t)(bm + row) * lda + kt * 64 + q * 8);
        }
#pragma unroll
        for (int i = 0; i < 4; i++) {
            int c = tid + i * 256;
            int row = c >> 3, q = c & 7;
            uint32_t dst = sBase + (s * STG + ASTG + row * SPH) * 2 + q * 16;
            CP_ASYNC16(dst, W + (size_t)(bn + row) * ldw + kt * 64 + q * 8);
        }
        CP_COMMIT();
    };

    prefetch(0); prefetch(1);               // nK >= 2 at all call sites

    for (int kt = 0; kt < nK; kt++) {
        cp_wait<1>();                        // stage kt landed (invariant)
        __syncthreads();                     // stage (kt-1) reads done
        if (kt + 2 < nK) prefetch(kt + 2);
        else CP_COMMIT();                    // one-commit-per-iter invariant

        const uint32_t base = sBase + (kt % 3) * STG * 2;
#pragma unroll
        for (int g = 0; g < 4; g++) {        // four k16 groups per k-tile
            uint32_t a[4][4], b[4][2];
#pragma unroll
            for (int mt = 0; mt < 4; mt++) {
                int r = wm + mt * 16 + (lane & 15);
                uint32_t ad = base + (r * SPH + g * 16 + ((lane >> 4) << 3)) * 2;
                LDSM_X4(a[mt], ad);
            }
#pragma unroll
            for (int nt = 0; nt < 4; nt++) {
                int r = wn + nt * 8 + (lane & 7);
                uint32_t ad = base + (ASTG + r * SPH + g * 16 + (((lane >> 3) & 1) << 3)) * 2;
                LDSM_X2(b[nt], ad);
            }
#pragma unroll
            for (int mt = 0; mt < 4; mt++)
#pragma unroll
                for (int nt = 0; nt < 4; nt++)
                    mma_f16(acc[mt][nt], a[mt], b[nt]);
        }
    }

    // ---- epilogue ----
#pragma unroll
    for (int mt = 0; mt < 4; mt++) {
        const int r0 = bm + wm + mt * 16 + (lane >> 2);
#pragma unroll
        for (int nt = 0; nt < 4; nt++) {
            const int c0 = bn + wn + nt * 8 + (lane & 3) * 2;
            const float b0 = bias[c0], b1 = bias[c0 + 1];
            if constexpr (sizeof(OutT) == 4) {
                float* p0 = (float*)C + (size_t)r0 * ldc + c0;
                float* p1 = (float*)C + (size_t)(r0 + 8) * ldc + c0;
                float2 v0 = make_float2(acc[mt][nt][0] + b0, acc[mt][nt][1] + b1);
                float2 v1 = make_float2(acc[mt][nt][2] + b0, acc[mt][nt][3] + b1);
                if constexpr (ACC) {
                    float2 o0 = *(float2*)p0, o1 = *(float2*)p1;
                    v0.x += o0.x; v0.y += o0.y; v1.x += o1.x; v1.y += o1.y;
                }
                *(float2*)p0 = v0;
                *(float2*)p1 = v1;
            } else {
                __half2 v0 = __floats2half2_rn(acc[mt][nt][0] + b0, acc[mt][nt][1] + b1);
                __half2 v1 = __floats2half2_rn(acc[mt][nt][2] + b0, acc[mt][nt][3] + b1);
                *(__half2*)((__half*)C + (size_t)r0 * ldc + c0) = v0;
                *(__half2*)((__half*)C + (size_t)(r0 + 8) * ldc + c0) = v1;
            }
        }
    }
}

// =====================================================================
// Fused RVQ tail: softmax(logits/tau) -> fp16 w (smem) -> e = w @ ET^T (mma)
//                 -> step += e ; cum += e ; dec tail = fp16(cum)
// One CTA = 32 batch rows, 256 threads. ET streamed via 3-stage cp.async.
// =====================================================================
#define WROW 1032                            // w smem row stride (halves)
#define ESTG (128 * SPH)                     // E halves per stage

__global__ void __launch_bounds__(256, 1)
rvq_fused(const float* __restrict__ logits,
          const __half* __restrict__ ET,
          float* __restrict__ cum,
          __half* __restrict__ dec_h,
          float* __restrict__ step_out, int q)
{
    extern __shared__ __half smh[];          // w: 32*WROW ; E: 3*ESTG
    __half* wsm = smh;
    __half* esm = smh + 32 * WROW;

    const int tid = threadIdx.x, lane = tid & 31, wid = tid >> 5;
    const size_t rowBase = (size_t)blockIdx.x * 32;
    const uint32_t wB = smem_u32(wsm);
    const uint32_t eB = smem_u32(esm);

    auto prefE = [&](int kc) {
        const int s = kc % 3;
#pragma unroll
        for (int i = 0; i < 4; i++) {
            int c = tid + i * 256;
            int row = c >> 3, qk = c & 7;
            uint32_t dst = eB + (s * ESTG + row * SPH) * 2 + qk * 16;
            CP_ASYNC16(dst, ET + (size_t)row * KCB + kc * 64 + qk * 8);
        }
        CP_COMMIT();
    };
    prefE(0); prefE(1);

    // ---- softmax phase: warp handles rows wid*4 .. wid*4+3 ----
#pragma unroll
    for (int rr = 0; rr < 4; rr++) {
        const int row = wid * 4 + rr;
        const float* lr = logits + (rowBase + row) * KCB;
        float v[32];
        float m = -INFINITY;
#pragma unroll
        for (int i = 0; i < 32; i++) { v[i] = lr[lane + 32*i]; m = fmaxf(m, v[i]); }
#pragma unroll
        for (int o = 16; o; o >>= 1) m = fmaxf(m, __shfl_xor_sync(0xffffffffu, m, o));
        float s = 0.f;
#pragma unroll
        for (int i = 0; i < 32; i++) { v[i] = expf((v[i] - m) * INV_TAU); s += v[i]; }
#pragma unroll
        for (int o = 16; o; o >>= 1) s += __shfl_xor_sync(0xffffffffu, s, o);
        float inv = 1.f / s;
#pragma unroll
        for (int i = 0; i < 32; i++)
            wsm[row * WROW + lane + 32*i] = __float2half_rn(v[i] * inv);
    }

    // ---- mma phase: e[32,128] = w[32,1024] @ ET[128,1024]^T ----
    const int wm = (wid >> 2) * 16, wn = (wid & 3) * 32;
    float acc[4][4];
#pragma unroll
    for (int j = 0; j < 4; j++)
#pragma unroll
        for (int k = 0; k < 4; k++) acc[j][k] = 0.f;

    for (int kc = 0; kc < KCB / 64; kc++) {
        cp_wait<1>();
        __syncthreads();                      // also orders softmax writes (kc==0)
        if (kc + 2 < KCB / 64) prefE(kc + 2);
        else CP_COMMIT();                     // one-commit-per-iter invariant

        const uint32_t ebase = eB + (kc % 3) * ESTG * 2;
#pragma unroll
        for (int g = 0; g < 4; g++) {
            uint32_t a[4], b[4][2];
            {
                int r = wm + (lane & 15);
                uint32_t ad = wB + (r * WROW + kc * 64 + g * 16 + ((lane >> 4) << 3)) * 2;
                LDSM_X4(a, ad);
            }
#pragma unroll
            for (int nt = 0; nt < 4; nt++) {
                int r = wn + nt * 8 + (lane & 7);
                uint32_t ad = ebase + (r * SPH + g * 16 + (((lane >> 3) & 1) << 3)) * 2;
                LDSM_X2(b[nt], ad);
            }
#pragma unroll
            for (int nt = 0; nt < 4; nt++)
                mma_f16(acc[nt], a, b[nt]);
        }
    }

    // ---- update epilogue ----
    const int r0 = wm + (lane >> 2);
#pragma unroll
    for (int nt = 0; nt < 4; nt++) {
        const int c0 = wn + nt * 8 + (lane & 3) * 2;
#pragma unroll
        for (int half = 0; half < 2; half++) {
            const int r = r0 + half * 8;
            const size_t b = rowBase + r;
#pragma unroll
            for (int cc = 0; cc < 2; cc++) {
                const int c = c0 + cc;
                const float eV = acc[nt][half * 2 + cc];
                const size_t idx = b * D_IN + c;
                float sp = (q == 0) ? 0.f : step_out[idx];
                step_out[idx] = sp + eV;
                if (q < NQ - 1) {
                    float cv = (q == 0) ? 0.f : cum[idx];
                    cv += eV;
                    cum[idx] = cv;
                    dec_h[b * DECK + HID + c] = __float2half_rn(cv);
                }
            }
        }
    }
}

// =====================================================================
// merged fp32 -> fp16 convert of all four operand blocks (one launch)
// =====================================================================
#define CVN_W  ((size_t)NLAY * H3 * HID / 4)     // wih (== whh)
#define CVN_D  ((size_t)NQ * KCB * DECK / 4)     // dec_w
#define CVN_H  ((size_t)NLAY * BATCH * HID / 4)  // hidden
#define CVN_TOT (2 * CVN_W + CVN_D + CVN_H)

__device__ __forceinline__ void cv4(const float4* s, uint2* d, size_t i) {
    float4 v = s[i];
    __half2 h01 = __floats2half2_rn(v.x, v.y);
    __half2 h23 = __floats2half2_rn(v.z, v.w);
    uint2 u; u.x = *(uint32_t*)&h01; u.y = *(uint32_t*)&h23;
    d[i] = u;
}

__global__ void conv_all(const float4* __restrict__ wih, uint2* __restrict__ wih_h,
                         const float4* __restrict__ whh, uint2* __restrict__ whh_h,
                         const float4* __restrict__ dw,  uint2* __restrict__ dw_h,
                         const float4* __restrict__ hid, uint2* __restrict__ hid_h)
{
    size_t i = (size_t)blockIdx.x * blockDim.x + threadIdx.x;
    if (i < CVN_W)                     { cv4(wih, wih_h, i); return; }
    i -= CVN_W;
    if (i < CVN_W)                     { cv4(whh, whh_h, i); return; }
    i -= CVN_W;
    if (i < CVN_D)                     { cv4(dw, dw_h, i); return; }
    i -= CVN_D;
    if (i < CVN_H)                     { cv4(hid, hid_h, i); }
}

// =====================================================================
// lat_w (LPN=512, D_IN=128) fp32 -> latwT (D_IN=128, LPN=512) fp16
// =====================================================================
__global__ void transpose_latw(const float* __restrict__ lat_w, __half* __restrict__ latwT)
{
    __shared__ float t[32][33];
    int n0 = blockIdx.x * 32, d0 = blockIdx.y * 32;
#pragma unroll
    for (int i = 0; i < 32; i += 8)
        t[threadIdx.y + i][threadIdx.x] =
            lat_w[(size_t)(n0 + threadIdx.y + i) * D_IN + d0 + threadIdx.x];
    __syncthreads();
#pragma unroll
    for (int i = 0; i < 32; i += 8)
        latwT[(size_t)(d0 + threadIdx.y + i) * LPN + n0 + threadIdx.x] =
            __float2half_rn(t[threadIdx.x][threadIdx.y + i]);
}

// =====================================================================
// cond-part of fused layer-0 weight + effective bias (float4-vectorized).
// One warp per output row j (H3 rows).
// =====================================================================
__global__ void fuse_cond_bias(const float* __restrict__ gwih0,
                               const float* __restrict__ cond_w,
                               const float* __restrict__ lat_b,
                               const float* __restrict__ cond_b,
                               const float* __restrict__ gbih0,
                               __half* __restrict__ Wfull,
                               float* __restrict__ b_eff)
{
    int gw = (blockIdx.x * blockDim.x + threadIdx.x) >> 5;   // row j
    int lane = threadIdx.x & 31;
    const float4* wr = (const float4*)(gwih0 + (size_t)gw * HID);
    float c0 = 0.f, c1 = 0.f, c2 = 0.f, bl = 0.f, bc = 0.f;
#pragma unroll
    for (int i = lane; i < 128; i += 32) {
        float4 wl = wr[i];
        float4 lb = ((const float4*)lat_b)[i];
        bl += wl.x*lb.x + wl.y*lb.y + wl.z*lb.z + wl.w*lb.w;
        float4 wc = wr[128 + i];
        float4 cb = ((const float4*)cond_b)[i];
        bc += wc.x*cb.x + wc.y*cb.y + wc.z*cb.z + wc.w*cb.w;
        const float* cw = cond_w + 12 * i;   // cond_w rows 4i..4i+3
        c0 += wc.x*cw[0] + wc.y*cw[3] + wc.z*cw[6] + wc.w*cw[9];
        c1 += wc.x*cw[1] + wc.y*cw[4] + wc.z*cw[7] + wc.w*cw[10];
        c2 += wc.x*cw[2] + wc.y*cw[5] + wc.z*cw[8] + wc.w*cw[11];
    }
#pragma unroll
    for (int o = 16; o; o >>= 1) {
        c0 += __shfl_xor_sync(0xffffffffu, c0, o);
        c1 += __shfl_xor_sync(0xffffffffu, c1, o);
        c2 += __shfl_xor_sync(0xffffffffu, c2, o);
        bl += __shfl_xor_sync(0xffffffffu, bl, o);
        bc += __shfl_xor_sync(0xffffffffu, bc, o);
    }
    if (lane == 0) {
        __half* wf = Wfull + (size_t)gw * DPAD;
        wf[128] = __float2half_rn(c0);
        wf[129] = __float2half_rn(c1);
        wf[130] = __float2half_rn(c2);
        b_eff[gw] = gbih0[gw] + bl + bc;
    }
}

// pad x (B x 131 fp32, unaligned) -> xpad (B x 192 fp16, zero tail)
__global__ void pad_x(const float* __restrict__ x, __half* __restrict__ xpad)
{
    int idx = blockIdx.x * blockDim.x + threadIdx.x;   // BATCH * DPAD
    int b = idx / DPAD, c = idx - b * DPAD;
    float v = (c < D_IN + D_COND) ? x[(size_t)b * (D_IN + D_COND) + c] : 0.f;
    xpad[(size_t)b * DPAD + c] = __float2half_rn(v);
}

__device__ __forceinline__ float sigm(float v) { return 1.f / (1.f + expf(-v)); }

// GRU gates from fp16 gi/gh; fp32 h to output, fp16 h to next-layer + dec head.
__global__ void gru_gate(const __half* __restrict__ gi,
                         const __half* __restrict__ gh,
                         const float* __restrict__ hprev,
                         float* __restrict__ hout,
                         __half* __restrict__ xl_h,
                         __half* __restrict__ dec_h, int writeDec)
{
    int idx = blockIdx.x * blockDim.x + threadIdx.x;   // BATCH * 256
    int b = idx >> 8, j4 = idx & 255;
    const __half2* gib = (const __half2*)(gi + (size_t)b * H3);
    const __half2* ghb = (const __half2*)(gh + (size_t)b * H3);
    float2 ir0 = __half22float2(gib[j4*2]),        ir1 = __half22float2(gib[j4*2+1]);
    float2 iz0 = __half22float2(gib[512 + j4*2]),  iz1 = __half22float2(gib[512 + j4*2+1]);
    float2 in0 = __half22float2(gib[1024 + j4*2]), in1 = __half22float2(gib[1024 + j4*2+1]);
    float2 hr0 = __half22float2(ghb[j4*2]),        hr1 = __half22float2(ghb[j4*2+1]);
    float2 hz0 = __half22float2(ghb[512 + j4*2]),  hz1 = __half22float2(ghb[512 + j4*2+1]);
    float2 hn0 = __half22float2(ghb[1024 + j4*2]), hn1 = __half22float2(ghb[1024 + j4*2+1]);
    float4 hp = ((const float4*)hprev)[idx];
    float4 h;
    {
        float r = sigm(ir0.x + hr0.x), z = sigm(iz0.x + hz0.x);
        float n = tanhf(in0.x + r * hn0.x); h.x = (1.f - z) * n + z * hp.x;
    }{
        float r = sigm(ir0.y + hr0.y), z = sigm(iz0.y + hz0.y);
        float n = tanhf(in0.y + r * hn0.y); h.y = (1.f - z) * n + z * hp.y;
    }{
        float r = sigm(ir1.x + hr1.x), z = sigm(iz1.x + hz1.x);
        float n = tanhf(in1.x + r * hn1.x); h.z = (1.f - z) * n + z * hp.z;
    }{
        float r = sigm(ir1.y + hr1.y), z = sigm(iz1.y + hz1.y);
        float n = tanhf(in1.y + r * hn1.y); h.w = (1.f - z) * n + z * hp.w;
    }
    ((float4*)hout)[idx] = h;
    __half2 h01 = __floats2half2_rn(h.x, h.y);
    __half2 h23 = __floats2half2_rn(h.z, h.w);
    uint2 u; u.x = *(uint32_t*)&h01; u.y = *(uint32_t*)&h23;
    ((uint2*)xl_h)[idx] = u;
    if (writeDec) ((uint2*)dec_h)[(size_t)b * (DECK/4) + j4] = u;
}

// E (NQ,K,D_IN) -> ET_h (NQ,D_IN,K) fp16
__global__ void transposeE(const float* __restrict__ E, __half* __restrict__ ET)
{
    __shared__ float t[32][33];
    int q = blockIdx.z;
    int k0 = blockIdx.x * 32, n0 = blockIdx.y * 32;
    const float* Eq = E + (size_t)q * KCB * D_IN;
    __half* Tq = ET + (size_t)q * D_IN * KCB;
#pragma unroll
    for (int i = 0; i < 32; i += 8)
        t[threadIdx.y + i][threadIdx.x] =
            Eq[(size_t)(k0 + threadIdx.y + i) * D_IN + n0 + threadIdx.x];
    __syncthreads();
#pragma unroll
    for (int i = 0; i < 32; i += 8)
        Tq[(size_t)(n0 + threadIdx.y + i) * KCB + k0 + threadIdx.x] =
            __float2half_rn(t[threadIdx.x][threadIdx.y + i]);
}

// =====================================================================
extern "C" void kernel_launch(void* const* d_in, const int* in_sizes, int n_in,
                              void* d_out, int out_size)
{
    const float* x      = (const float*)d_in[0];
    const float* hidden = (const float*)d_in[1];
    const float* lat_w  = (const float*)d_in[2];
    const float* lat_b  = (const float*)d_in[3];
    const float* cond_w = (const float*)d_in[4];
    const float* cond_b = (const float*)d_in[5];
    const float* gwih   = (const float*)d_in[6];
    const float* gwhh   = (const float*)d_in[7];
    const float* gbih   = (const float*)d_in[8];
    const float* gbhh   = (const float*)d_in[9];
    const float* dec_w  = (const float*)d_in[10];
    const float* dec_b  = (const float*)d_in[11];
    const float* E_eff  = (const float*)d_in[12];

    const size_t BH  = (size_t)BATCH * HID;
    const size_t BH3 = (size_t)BATCH * H3;
    const size_t BK  = (size_t)BATCH * KCB;

    float* out_logits = (float*)d_out;
    float* out_hidden = out_logits + (size_t)NQ * BK;
    float* out_step   = out_hidden + (size_t)NLAY * BH;

    float *cum, *beff, *zerof;
    __half *gi, *gh, *xl_h, *hid_h, *wih_h, *whh_h, *dw_h, *ET_h, *dec_h;
    __half *Wfull, *latwT, *xpad;
    cudaGetSymbolAddress((void**)&cum,   g_cum);
    cudaGetSymbolAddress((void**)&beff,  g_beff);
    cudaGetSymbolAddress((void**)&zerof, g_zerof);
    cudaGetSymbolAddress((void**)&gi,    g_gi);
    cudaGetSymbolAddress((void**)&gh,    g_gh);
    cudaGetSymbolAddress((void**)&xl_h,  g_xl_h);
    cudaGetSymbolAddress((void**)&hid_h, g_hid_h);
    cudaGetSymbolAddress((void**)&wih_h, g_wih_h);
    cudaGetSymbolAddress((void**)&whh_h, g_whh_h);
    cudaGetSymbolAddress((void**)&dw_h,  g_dw_h);
    cudaGetSymbolAddress((void**)&ET_h,  g_ET_h);
    cudaGetSymbolAddress((void**)&dec_h, g_dec_h);
    cudaGetSymbolAddress((void**)&Wfull, g_Wfull);
    cudaGetSymbolAddress((void**)&latwT, g_latwT);
    cudaGetSymbolAddress((void**)&xpad,  g_xpad);

    const int SMEM_G = 3 * 2 * 128 * SPH * 2;            // 110592 B
    const int SMEM_R = (32 * WROW + 3 * 128 * SPH) * 2;  // 121344 B
    cudaFuncSetAttribute((hgemm<float, false>),  cudaFuncAttributeMaxDynamicSharedMemorySize, SMEM_G);
    cudaFuncSetAttribute((hgemm<float, true>),   cudaFuncAttributeMaxDynamicSharedMemorySize, SMEM_G);
    cudaFuncSetAttribute((hgemm<__half, false>), cudaFuncAttributeMaxDynamicSharedMemorySize, SMEM_G);
    cudaFuncSetAttribute(rvq_fused, cudaFuncAttributeMaxDynamicSharedMemorySize, SMEM_R);

    // ---- operand pre-conversion: ONE launch ----
    conv_all<<<(int)((CVN_TOT + 255) / 256), 256>>>(
        (const float4*)gwih, (uint2*)wih_h,
        (const float4*)gwhh, (uint2*)whh_h,
        (const float4*)dec_w, (uint2*)dw_h,
        (const float4*)hidden, (uint2*)hid_h);

    // ---- fused layer-0 input weights ----
    transpose_latw<<<dim3(LPN/32, D_IN/32), dim3(32, 8)>>>(lat_w, latwT);
    hgemm<__half, false><<<dim3(1, H3/128), 256, SMEM_G>>>(
        wih_h, HID, 0,
        latwT, LPN, 0,
        zerof, 0,
        Wfull, DPAD, 0, LPN);
    fuse_cond_bias<<<H3/8, 256>>>(gwih, cond_w, lat_b, cond_b, gbih, Wfull, beff);
    pad_x<<<(BATCH*DPAD)/256, 256>>>(x, xpad);

    // ---- E transpose -> fp16 ----
    transposeE<<<dim3(KCB/32, D_IN/32, NQ), dim3(32, 8)>>>(E_eff, ET_h);

    // ---- all 4 gh GEMMs in ONE z-batched launch ----
    hgemm<__half, false><<<dim3(H3/128, BATCH/128, NLAY), 256, SMEM_G>>>(
        hid_h, HID, BH,
        whh_h, HID, (size_t)H3 * HID,
        gbhh, H3,
        gh, H3, BH3, HID);

    // ---- 4-layer GRU chain ----
    for (int l = 0; l < NLAY; l++) {
        if (l == 0) {
            hgemm<__half, false><<<dim3(H3/128, BATCH/128), 256, SMEM_G>>>(
                xpad, DPAD, 0,
                Wfull, DPAD, 0,
                beff, 0,
                gi, H3, 0, DPAD);
        } else {
            hgemm<__half, false><<<dim3(H3/128, BATCH/128), 256, SMEM_G>>>(
                xl_h, HID, 0,
                wih_h + (size_t)l * H3 * HID, HID, 0,
                gbih + (size_t)l * H3, 0,
                gi, H3, 0, HID);
        }
        gru_gate<<<(int)(BH/4/256), 256>>>(
            gi, gh + (size_t)l * BH3, hidden + (size_t)l * BH,
            out_hidden + (size_t)l * BH, xl_h, dec_h, (l == NLAY-1) ? 1 : 0);
    }

    // ---- decoder head: all 8 q's in ONE z-batched GEMM (K=1024, h part) ----
    hgemm<float, false><<<dim3(KCB/128, BATCH/128, NQ), 256, SMEM_G>>>(
        dec_h, DECK, 0,
        dw_h, DECK, (size_t)KCB * DECK,
        dec_b, KCB,
        out_logits, KCB, BK, HID);

    // ---- RVQ cascade: per-q tail (K=128, cum part, accumulate) + fused update ----
    for (int q = 0; q < NQ; q++) {
        if (q > 0) {
            hgemm<float, true><<<dim3(KCB/128, BATCH/128), 256, SMEM_G>>>(
                dec_h + HID, DECK, 0,
                dw_h + (size_t)q * KCB * DECK + HID, DECK, 0,
                zerof, 0,
                out_logits + (size_t)q * BK, KCB, 0, D_IN);
        }
        rvq_fused<<<BATCH/32, 256, SMEM_R>>>(
            out_logits + (size_t)q * BK, ET_h + (size_t)q * D_IN * KCB,
            cum, dec_h, out_step, q);
    }
}

// round 16
// speedup vs baseline: 1.0480x; 1.0480x over previous
#include <cuda_runtime.h>
#include <cuda_fp16.h>
#include <math.h>
#include <stdint.h>

// ---------------- problem constants ----------------
#define BATCH   8192
#define D_IN    128
#define D_COND  3
#define HID     1024
#define NLAY    4
#define NQ      8
#define KCB     1024
#define H3      (3*HID)        // 3072
#define DECK    (HID + D_IN)   // 1152
#define LPN     512
#define DPAD    192            // padded K for fused layer-0 input GEMM
#define INV_TAU (1.0f/0.6f)

// ---------------- scratch (no allocation allowed) ----------------
__device__ float  g_cum  [(size_t)BATCH * D_IN];
__device__ float  g_beff [H3];                        // fused layer-0 bias
__device__ float  g_zerof[1024];                      // stays 0 (never written)
// fp16 buffers
__device__ __half g_gi   [(size_t)BATCH * H3];
__device__ __half g_gh   [(size_t)NLAY * BATCH * H3];
__device__ __half g_xl_h [(size_t)BATCH * HID];
__device__ __half g_hid_h[(size_t)NLAY * BATCH * HID];
__device__ __half g_wih_h[(size_t)NLAY * H3 * HID];
__device__ __half g_whh_h[(size_t)NLAY * H3 * HID];
__device__ __half g_dw_h [(size_t)NQ * KCB * DECK];
__device__ __half g_ET_h [(size_t)NQ * D_IN * KCB];
__device__ __half g_dec_h[(size_t)BATCH * DECK];      // [h | cum]
__device__ __half g_Wfull[(size_t)H3 * DPAD];         // fused layer-0 weight (cols 131..191 stay 0)
__device__ __half g_latwT[(size_t)D_IN * LPN];        // lat_w transposed fp16
__device__ __half g_xpad [(size_t)BATCH * DPAD];      // padded fp16 x

// =====================================================================
__device__ __forceinline__ uint32_t smem_u32(const void* p) {
    uint32_t a;
    asm("{ .reg .u64 t; cvta.to.shared.u64 t, %1; cvt.u32.u64 %0, t; }" : "=r"(a) : "l"(p));
    return a;
}
#define CP_ASYNC16(dst, src) \
    asm volatile("cp.async.cg.shared.global [%0], [%1], 16;" :: "r"(dst), "l"(src) : "memory")
#define CP_COMMIT() asm volatile("cp.async.commit_group;" ::: "memory")
template <int N> __device__ __forceinline__ void cp_wait() {
    asm volatile("cp.async.wait_group %0;" :: "n"(N) : "memory");
}
#define LDSM_X4(r, addr) \
    asm volatile("ldmatrix.sync.aligned.m8n8.x4.shared.b16 {%0,%1,%2,%3}, [%4];" \
        : "=r"((r)[0]), "=r"((r)[1]), "=r"((r)[2]), "=r"((r)[3]) : "r"(addr))
#define LDSM_X2(r, addr) \
    asm volatile("ldmatrix.sync.aligned.m8n8.x2.shared.b16 {%0,%1}, [%2];" \
        : "=r"((r)[0]), "=r"((r)[1]) : "r"(addr))

__device__ __forceinline__ void mma_f16(float* c, const uint32_t* a, const uint32_t* b) {
    asm volatile(
        "mma.sync.aligned.m16n8k16.row.col.f32.f16.f16.f32 "
        "{%0,%1,%2,%3}, {%4,%5,%6,%7}, {%8,%9}, {%0,%1,%2,%3};"
        : "+f"(c[0]), "+f"(c[1]), "+f"(c[2]), "+f"(c[3])
        : "r"(a[0]), "r"(a[1]), "r"(a[2]), "r"(a[3]), "r"(b[0]), "r"(b[1]));
}

// =====================================================================
// fp16 mma.sync GEMM (z-batched): C[M,N] = A[M,K] @ W[N,K]^T + bias[N]
//   BM=BN=128, BK=64, 256 threads (8 warps: 2m x 4n), warp tile 64x32.
//   3-stage cp.async pipeline; EVERY iteration commits a group (empty in
//   the tail) so wait_group<1> at iteration kt proves stage kt landed.
//   OutT = float or __half. Requires K%64==0, nK>=2, M%128==0, N%128==0.
// =====================================================================
#define SPH 72                              // halves per smem row (64 + 8 pad)

template <typename OutT>
__global__ void __launch_bounds__(256, 2)
hgemm(const __half* __restrict__ A, int lda, size_t zsA,
      const __half* __restrict__ W, int ldw, size_t zsW,
      const float* __restrict__ bias, size_t zsB,
      OutT* __restrict__ C, int ldc, size_t zsC, int K)
{
    constexpr int ASTG = 128 * SPH;
    constexpr int STG  = 2 * ASTG;

    extern __shared__ __half smh[];         // [3][STG]

    A    += (size_t)blockIdx.z * zsA;
    W    += (size_t)blockIdx.z * zsW;
    bias += (size_t)blockIdx.z * zsB;
    C    += (size_t)blockIdx.z * zsC;

    const int tid = threadIdx.x, lane = tid & 31, wid = tid >> 5;
    const int bm = blockIdx.y * 128, bn = blockIdx.x * 128;
    const int wm = (wid >> 2) * 64, wn = (wid & 3) * 32;
    const uint32_t sBase = smem_u32(smh);

    float acc[4][4][4];
#pragma unroll
    for (int i = 0; i < 4; i++)
#pragma unroll
        for (int j = 0; j < 4; j++)
#pragma unroll
            for (int k = 0; k < 4; k++) acc[i][j][k] = 0.f;

    const int nK = K / 64;

    auto prefetch = [&](int kt) {
        const int s = kt % 3;
#pragma unroll
        for (int i = 0; i < 4; i++) {
            int c = tid + i * 256;
            int row = c >> 3, q = c & 7;
            uint32_t dst = sBase + (s * STG + row * SPH) * 2 + q * 16;
            CP_ASYNC16(dst, A + (size_t)(bm + row) * lda + kt * 64 + q * 8);
        }
#pragma unroll
        for (int i = 0; i < 4; i++) {
            int c = tid + i * 256;
            int row = c >> 3, q = c & 7;
            uint32_t dst = sBase + (s * STG + ASTG + row * SPH) * 2 + q * 16;
            CP_ASYNC16(dst, W + (size_t)(bn + row) * ldw + kt * 64 + q * 8);
        }
        CP_COMMIT();
    };

    prefetch(0); prefetch(1);               // nK >= 2 at all call sites

    for (int kt = 0; kt < nK; kt++) {
        cp_wait<1>();                        // stage kt landed (invariant)
        __syncthreads();                     // stage (kt-1) reads done
        if (kt + 2 < nK) prefetch(kt + 2);
        else CP_COMMIT();                    // one-commit-per-iter invariant

        const uint32_t base = sBase + (kt % 3) * STG * 2;
#pragma unroll
        for (int g = 0; g < 4; g++) {        // four k16 groups per k-tile
            uint32_t a[4][4], b[4][2];
#pragma unroll
            for (int mt = 0; mt < 4; mt++) {
                int r = wm + mt * 16 + (lane & 15);
                uint32_t ad = base + (r * SPH + g * 16 + ((lane >> 4) << 3)) * 2;
                LDSM_X4(a[mt], ad);
            }
#pragma unroll
            for (int nt = 0; nt < 4; nt++) {
                int r = wn + nt * 8 + (lane & 7);
                uint32_t ad = base + (ASTG + r * SPH + g * 16 + (((lane >> 3) & 1) << 3)) * 2;
                LDSM_X2(b[nt], ad);
            }
#pragma unroll
            for (int mt = 0; mt < 4; mt++)
#pragma unroll
                for (int nt = 0; nt < 4; nt++)
                    mma_f16(acc[mt][nt], a[mt], b[nt]);
        }
    }

    // ---- epilogue ----
#pragma unroll
    for (int mt = 0; mt < 4; mt++) {
        const int r0 = bm + wm + mt * 16 + (lane >> 2);
#pragma unroll
        for (int nt = 0; nt < 4; nt++) {
            const int c0 = bn + wn + nt * 8 + (lane & 3) * 2;
            const float b0 = bias[c0], b1 = bias[c0 + 1];
            if constexpr (sizeof(OutT) == 4) {
                float2 v0 = make_float2(acc[mt][nt][0] + b0, acc[mt][nt][1] + b1);
                float2 v1 = make_float2(acc[mt][nt][2] + b0, acc[mt][nt][3] + b1);
                *(float2*)((float*)C + (size_t)r0 * ldc + c0) = v0;
                *(float2*)((float*)C + (size_t)(r0 + 8) * ldc + c0) = v1;
            } else {
                __half2 v0 = __floats2half2_rn(acc[mt][nt][0] + b0, acc[mt][nt][1] + b1);
                __half2 v1 = __floats2half2_rn(acc[mt][nt][2] + b0, acc[mt][nt][3] + b1);
                *(__half2*)((__half*)C + (size_t)r0 * ldc + c0) = v0;
                *(__half2*)((__half*)C + (size_t)(r0 + 8) * ldc + c0) = v1;
            }
        }
    }
}

// =====================================================================
// Fused RVQ tail: softmax(logits/tau) -> fp16 w (smem) -> e = w @ ET^T (mma)
//                 -> step += e ; cum += e ; dec tail = fp16(cum)
// One CTA = 32 batch rows, 256 threads. ET streamed via 2-stage cp.async
// (prefetch-1-ahead; smem 102.9KB -> 2 CTAs/SM -> whole grid resident).
// =====================================================================
#define WROW 1032                            // w smem row stride (halves)
#define ESTG (128 * SPH)                     // E halves per stage

__global__ void __launch_bounds__(256, 2)
rvq_fused(const float* __restrict__ logits,
          const __half* __restrict__ ET,
          float* __restrict__ cum,
          __half* __restrict__ dec_h,
          float* __restrict__ step_out, int q)
{
    extern __shared__ __half smh[];          // w: 32*WROW ; E: 2*ESTG
    __half* wsm = smh;
    __half* esm = smh + 32 * WROW;

    const int tid = threadIdx.x, lane = tid & 31, wid = tid >> 5;
    const size_t rowBase = (size_t)blockIdx.x * 32;
    const uint32_t wB = smem_u32(wsm);
    const uint32_t eB = smem_u32(esm);

    auto prefE = [&](int kc) {
        const int s = kc & 1;
#pragma unroll
        for (int i = 0; i < 4; i++) {
            int c = tid + i * 256;
            int row = c >> 3, qk = c & 7;
            uint32_t dst = eB + (s * ESTG + row * SPH) * 2 + qk * 16;
            CP_ASYNC16(dst, ET + (size_t)row * KCB + kc * 64 + qk * 8);
        }
        CP_COMMIT();
    };
    prefE(0);

    // ---- softmax phase: warp handles rows wid*4 .. wid*4+3 ----
#pragma unroll
    for (int rr = 0; rr < 4; rr++) {
        const int row = wid * 4 + rr;
        const float* lr = logits + (rowBase + row) * KCB;
        float v[32];
        float m = -INFINITY;
#pragma unroll
        for (int i = 0; i < 32; i++) { v[i] = lr[lane + 32*i]; m = fmaxf(m, v[i]); }
#pragma unroll
        for (int o = 16; o; o >>= 1) m = fmaxf(m, __shfl_xor_sync(0xffffffffu, m, o));
        float s = 0.f;
#pragma unroll
        for (int i = 0; i < 32; i++) { v[i] = expf((v[i] - m) * INV_TAU); s += v[i]; }
#pragma unroll
        for (int o = 16; o; o >>= 1) s += __shfl_xor_sync(0xffffffffu, s, o);
        float inv = 1.f / s;
#pragma unroll
        for (int i = 0; i < 32; i++)
            wsm[row * WROW + lane + 32*i] = __float2half_rn(v[i] * inv);
    }

    // ---- mma phase: e[32,128] = w[32,1024] @ ET[128,1024]^T ----
    const int wm = (wid >> 2) * 16, wn = (wid & 3) * 32;
    float acc[4][4];
#pragma unroll
    for (int j = 0; j < 4; j++)
#pragma unroll
        for (int k = 0; k < 4; k++) acc[j][k] = 0.f;

    for (int kc = 0; kc < KCB / 64; kc++) {
        cp_wait<0>();                         // stage kc fully landed
        __syncthreads();                      // stage (kc-1) reads done; softmax writes (kc==0)
        if (kc + 1 < KCB / 64) prefE(kc + 1); // overlaps with compute below

        const uint32_t ebase = eB + (kc & 1) * ESTG * 2;
#pragma unroll
        for (int g = 0; g < 4; g++) {
            uint32_t a[4], b[4][2];
            {
                int r = wm + (lane & 15);
                uint32_t ad = wB + (r * WROW + kc * 64 + g * 16 + ((lane >> 4) << 3)) * 2;
                LDSM_X4(a, ad);
            }
#pragma unroll
            for (int nt = 0; nt < 4; nt++) {
                int r = wn + nt * 8 + (lane & 7);
                uint32_t ad = ebase + (r * SPH + g * 16 + (((lane >> 3) & 1) << 3)) * 2;
                LDSM_X2(b[nt], ad);
            }
#pragma unroll
            for (int nt = 0; nt < 4; nt++)
                mma_f16(acc[nt], a, b[nt]);
        }
    }

    // ---- update epilogue ----
    const int r0 = wm + (lane >> 2);
#pragma unroll
    for (int nt = 0; nt < 4; nt++) {
        const int c0 = wn + nt * 8 + (lane & 3) * 2;
#pragma unroll
        for (int half = 0; half < 2; half++) {
            const int r = r0 + half * 8;
            const size_t b = rowBase + r;
#pragma unroll
            for (int cc = 0; cc < 2; cc++) {
                const int c = c0 + cc;
                const float eV = acc[nt][half * 2 + cc];
                const size_t idx = b * D_IN + c;
                float sp = (q == 0) ? 0.f : step_out[idx];
                step_out[idx] = sp + eV;
                if (q < NQ - 1) {
                    float cv = (q == 0) ? 0.f : cum[idx];
                    cv += eV;
                    cum[idx] = cv;
                    dec_h[b * DECK + HID + c] = __float2half_rn(cv);
                }
            }
        }
    }
}

// =====================================================================
// merged fp32 -> fp16 convert of all four operand blocks (one launch)
// =====================================================================
#define CVN_W  ((size_t)NLAY * H3 * HID / 4)     // wih (== whh)
#define CVN_D  ((size_t)NQ * KCB * DECK / 4)     // dec_w
#define CVN_H  ((size_t)NLAY * BATCH * HID / 4)  // hidden
#define CVN_TOT (2 * CVN_W + CVN_D + CVN_H)

__device__ __forceinline__ void cv4(const float4* s, uint2* d, size_t i) {
    float4 v = s[i];
    __half2 h01 = __floats2half2_rn(v.x, v.y);
    __half2 h23 = __floats2half2_rn(v.z, v.w);
    uint2 u; u.x = *(uint32_t*)&h01; u.y = *(uint32_t*)&h23;
    d[i] = u;
}

__global__ void conv_all(const float4* __restrict__ wih, uint2* __restrict__ wih_h,
                         const float4* __restrict__ whh, uint2* __restrict__ whh_h,
                         const float4* __restrict__ dw,  uint2* __restrict__ dw_h,
                         const float4* __restrict__ hid, uint2* __restrict__ hid_h)
{
    size_t i = (size_t)blockIdx.x * blockDim.x + threadIdx.x;
    if (i < CVN_W)                     { cv4(wih, wih_h, i); return; }
    i -= CVN_W;
    if (i < CVN_W)                     { cv4(whh, whh_h, i); return; }
    i -= CVN_W;
    if (i < CVN_D)                     { cv4(dw, dw_h, i); return; }
    i -= CVN_D;
    if (i < CVN_H)                     { cv4(hid, hid_h, i); }
}

// =====================================================================
// lat_w (LPN=512, D_IN=128) fp32 -> latwT (D_IN=128, LPN=512) fp16
// =====================================================================
__global__ void transpose_latw(const float* __restrict__ lat_w, __half* __restrict__ latwT)
{
    __shared__ float t[32][33];
    int n0 = blockIdx.x * 32, d0 = blockIdx.y * 32;
#pragma unroll
    for (int i = 0; i < 32; i += 8)
        t[threadIdx.y + i][threadIdx.x] =
            lat_w[(size_t)(n0 + threadIdx.y + i) * D_IN + d0 + threadIdx.x];
    __syncthreads();
#pragma unroll
    for (int i = 0; i < 32; i += 8)
        latwT[(size_t)(d0 + threadIdx.y + i) * LPN + n0 + threadIdx.x] =
            __float2half_rn(t[threadIdx.x][threadIdx.y + i]);
}

// =====================================================================
// cond-part of fused layer-0 weight + effective bias (float4-vectorized).
// One warp per output row j (H3 rows).
// =====================================================================
__global__ void fuse_cond_bias(const float* __restrict__ gwih0,
                               const float* __restrict__ cond_w,
                               const float* __restrict__ lat_b,
                               const float* __restrict__ cond_b,
                               const float* __restrict__ gbih0,
                               __half* __restrict__ Wfull,
                               float* __restrict__ b_eff)
{
    int gw = (blockIdx.x * blockDim.x + threadIdx.x) >> 5;   // row j
    int lane = threadIdx.x & 31;
    const float4* wr = (const float4*)(gwih0 + (size_t)gw * HID);
    float c0 = 0.f, c1 = 0.f, c2 = 0.f, bl = 0.f, bc = 0.f;
#pragma unroll
    for (int i = lane; i < 128; i += 32) {
        float4 wl = wr[i];
        float4 lb = ((const float4*)lat_b)[i];
        bl += wl.x*lb.x + wl.y*lb.y + wl.z*lb.z + wl.w*lb.w;
        float4 wc = wr[128 + i];
        float4 cb = ((const float4*)cond_b)[i];
        bc += wc.x*cb.x + wc.y*cb.y + wc.z*cb.z + wc.w*cb.w;
        const float* cw = cond_w + 12 * i;   // cond_w rows 4i..4i+3
        c0 += wc.x*cw[0] + wc.y*cw[3] + wc.z*cw[6] + wc.w*cw[9];
        c1 += wc.x*cw[1] + wc.y*cw[4] + wc.z*cw[7] + wc.w*cw[10];
        c2 += wc.x*cw[2] + wc.y*cw[5] + wc.z*cw[8] + wc.w*cw[11];
    }
#pragma unroll
    for (int o = 16; o; o >>= 1) {
        c0 += __shfl_xor_sync(0xffffffffu, c0, o);
        c1 += __shfl_xor_sync(0xffffffffu, c1, o);
        c2 += __shfl_xor_sync(0xffffffffu, c2, o);
        bl += __shfl_xor_sync(0xffffffffu, bl, o);
        bc += __shfl_xor_sync(0xffffffffu, bc, o);
    }
    if (lane == 0) {
        __half* wf = Wfull + (size_t)gw * DPAD;
        wf[128] = __float2half_rn(c0);
        wf[129] = __float2half_rn(c1);
        wf[130] = __float2half_rn(c2);
        b_eff[gw] = gbih0[gw] + bl + bc;
    }
}

// pad x (B x 131 fp32, unaligned) -> xpad (B x 192 fp16, zero tail)
__global__ void pad_x(const float* __restrict__ x, __half* __restrict__ xpad)
{
    int idx = blockIdx.x * blockDim.x + threadIdx.x;   // BATCH * DPAD
    int b = idx / DPAD, c = idx - b * DPAD;
    float v = (c < D_IN + D_COND) ? x[(size_t)b * (D_IN + D_COND) + c] : 0.f;
    xpad[(size_t)b * DPAD + c] = __float2half_rn(v);
}

__device__ __forceinline__ float sigm(float v) { return 1.f / (1.f + expf(-v)); }

// GRU gates from fp16 gi/gh; fp32 h to output, fp16 h to next-layer + dec head;
// also zeroes the dec tail on writeDec (graph replays need this every call).
__global__ void gru_gate(const __half* __restrict__ gi,
                         const __half* __restrict__ gh,
                         const float* __restrict__ hprev,
                         float* __restrict__ hout,
                         __half* __restrict__ xl_h,
                         __half* __restrict__ dec_h, int writeDec)
{
    int idx = blockIdx.x * blockDim.x + threadIdx.x;   // BATCH * 256
    int b = idx >> 8, j4 = idx & 255;
    const __half2* gib = (const __half2*)(gi + (size_t)b * H3);
    const __half2* ghb = (const __half2*)(gh + (size_t)b * H3);
    float2 ir0 = __half22float2(gib[j4*2]),        ir1 = __half22float2(gib[j4*2+1]);
    float2 iz0 = __half22float2(gib[512 + j4*2]),  iz1 = __half22float2(gib[512 + j4*2+1]);
    float2 in0 = __half22float2(gib[1024 + j4*2]), in1 = __half22float2(gib[1024 + j4*2+1]);
    float2 hr0 = __half22float2(ghb[j4*2]),        hr1 = __half22float2(ghb[j4*2+1]);
    float2 hz0 = __half22float2(ghb[512 + j4*2]),  hz1 = __half22float2(ghb[512 + j4*2+1]);
    float2 hn0 = __half22float2(ghb[1024 + j4*2]), hn1 = __half22float2(ghb[1024 + j4*2+1]);
    float4 hp = ((const float4*)hprev)[idx];
    float4 h;
    {
        float r = sigm(ir0.x + hr0.x), z = sigm(iz0.x + hz0.x);
        float n = tanhf(in0.x + r * hn0.x); h.x = (1.f - z) * n + z * hp.x;
    }{
        float r = sigm(ir0.y + hr0.y), z = sigm(iz0.y + hz0.y);
        float n = tanhf(in0.y + r * hn0.y); h.y = (1.f - z) * n + z * hp.y;
    }{
        float r = sigm(ir1.x + hr1.x), z = sigm(iz1.x + hz1.x);
        float n = tanhf(in1.x + r * hn1.x); h.z = (1.f - z) * n + z * hp.z;
    }{
        float r = sigm(ir1.y + hr1.y), z = sigm(iz1.y + hz1.y);
        float n = tanhf(in1.y + r * hn1.y); h.w = (1.f - z) * n + z * hp.w;
    }
    ((float4*)hout)[idx] = h;
    __half2 h01 = __floats2half2_rn(h.x, h.y);
    __half2 h23 = __floats2half2_rn(h.z, h.w);
    uint2 u; u.x = *(uint32_t*)&h01; u.y = *(uint32_t*)&h23;
    ((uint2*)xl_h)[idx] = u;
    if (writeDec) {
        ((uint2*)dec_h)[(size_t)b * (DECK/4) + j4] = u;
        if (j4 < 32)
            ((uint2*)dec_h)[(size_t)b * (DECK/4) + 256 + j4] = make_uint2(0, 0);
    }
}

// E (NQ,K,D_IN) -> ET_h (NQ,D_IN,K) fp16
__global__ void transposeE(const float* __restrict__ E, __half* __restrict__ ET)
{
    __shared__ float t[32][33];
    int q = blockIdx.z;
    int k0 = blockIdx.x * 32, n0 = blockIdx.y * 32;
    const float* Eq = E + (size_t)q * KCB * D_IN;
    __half* Tq = ET + (size_t)q * D_IN * KCB;
#pragma unroll
    for (int i = 0; i < 32; i += 8)
        t[threadIdx.y + i][threadIdx.x] =
            Eq[(size_t)(k0 + threadIdx.y + i) * D_IN + n0 + threadIdx.x];
    __syncthreads();
#pragma unroll
    for (int i = 0; i < 32; i += 8)
        Tq[(size_t)(n0 + threadIdx.y + i) * KCB + k0 + threadIdx.x] =
            __float2half_rn(t[threadIdx.x][threadIdx.y + i]);
}

// =====================================================================
extern "C" void kernel_launch(void* const* d_in, const int* in_sizes, int n_in,
                              void* d_out, int out_size)
{
    const float* x      = (const float*)d_in[0];
    const float* hidden = (const float*)d_in[1];
    const float* lat_w  = (const float*)d_in[2];
    const float* lat_b  = (const float*)d_in[3];
    const float* cond_w = (const float*)d_in[4];
    const float* cond_b = (const float*)d_in[5];
    const float* gwih   = (const float*)d_in[6];
    const float* gwhh   = (const float*)d_in[7];
    const float* gbih   = (const float*)d_in[8];
    const float* gbhh   = (const float*)d_in[9];
    const float* dec_w  = (const float*)d_in[10];
    const float* dec_b  = (const float*)d_in[11];
    const float* E_eff  = (const float*)d_in[12];

    const size_t BH  = (size_t)BATCH * HID;
    const size_t BH3 = (size_t)BATCH * H3;
    const size_t BK  = (size_t)BATCH * KCB;

    float* out_logits = (float*)d_out;
    float* out_hidden = out_logits + (size_t)NQ * BK;
    float* out_step   = out_hidden + (size_t)NLAY * BH;

    float *cum, *beff, *zerof;
    __half *gi, *gh, *xl_h, *hid_h, *wih_h, *whh_h, *dw_h, *ET_h, *dec_h;
    __half *Wfull, *latwT, *xpad;
    cudaGetSymbolAddress((void**)&cum,   g_cum);
    cudaGetSymbolAddress((void**)&beff,  g_beff);
    cudaGetSymbolAddress((void**)&zerof, g_zerof);
    cudaGetSymbolAddress((void**)&gi,    g_gi);
    cudaGetSymbolAddress((void**)&gh,    g_gh);
    cudaGetSymbolAddress((void**)&xl_h,  g_xl_h);
    cudaGetSymbolAddress((void**)&hid_h, g_hid_h);
    cudaGetSymbolAddress((void**)&wih_h, g_wih_h);
    cudaGetSymbolAddress((void**)&whh_h, g_whh_h);
    cudaGetSymbolAddress((void**)&dw_h,  g_dw_h);
    cudaGetSymbolAddress((void**)&ET_h,  g_ET_h);
    cudaGetSymbolAddress((void**)&dec_h, g_dec_h);
    cudaGetSymbolAddress((void**)&Wfull, g_Wfull);
    cudaGetSymbolAddress((void**)&latwT, g_latwT);
    cudaGetSymbolAddress((void**)&xpad,  g_xpad);

    const int SMEM_G = 3 * 2 * 128 * SPH * 2;            // 110592 B
    const int SMEM_R = (32 * WROW + 2 * 128 * SPH) * 2;  // 102912 B
    cudaFuncSetAttribute(hgemm<float>,  cudaFuncAttributeMaxDynamicSharedMemorySize, SMEM_G);
    cudaFuncSetAttribute(hgemm<__half>, cudaFuncAttributeMaxDynamicSharedMemorySize, SMEM_G);
    cudaFuncSetAttribute(rvq_fused, cudaFuncAttributeMaxDynamicSharedMemorySize, SMEM_R);

    // ---- operand pre-conversion: ONE launch ----
    conv_all<<<(int)((CVN_TOT + 255) / 256), 256>>>(
        (const float4*)gwih, (uint2*)wih_h,
        (const float4*)gwhh, (uint2*)whh_h,
        (const float4*)dec_w, (uint2*)dw_h,
        (const float4*)hidden, (uint2*)hid_h);

    // ---- fused layer-0 input weights ----
    transpose_latw<<<dim3(LPN/32, D_IN/32), dim3(32, 8)>>>(lat_w, latwT);
    hgemm<__half><<<dim3(1, H3/128), 256, SMEM_G>>>(
        wih_h, HID, 0,
        latwT, LPN, 0,
        zerof, 0,
        Wfull, DPAD, 0, LPN);
    fuse_cond_bias<<<H3/8, 256>>>(gwih, cond_w, lat_b, cond_b, gbih, Wfull, beff);
    pad_x<<<(BATCH*DPAD)/256, 256>>>(x, xpad);

    // ---- E transpose -> fp16 ----
    transposeE<<<dim3(KCB/32, D_IN/32, NQ), dim3(32, 8)>>>(E_eff, ET_h);

    // ---- all 4 gh GEMMs in ONE z-batched launch ----
    hgemm<__half><<<dim3(H3/128, BATCH/128, NLAY), 256, SMEM_G>>>(
        hid_h, HID, BH,
        whh_h, HID, (size_t)H3 * HID,
        gbhh, H3,
        gh, H3, BH3, HID);

    // ---- 4-layer GRU chain ----
    for (int l = 0; l < NLAY; l++) {
        if (l == 0) {
            hgemm<__half><<<dim3(H3/128, BATCH/128), 256, SMEM_G>>>(
                xpad, DPAD, 0,
                Wfull, DPAD, 0,
                beff, 0,
                gi, H3, 0, DPAD);
        } else {
            hgemm<__half><<<dim3(H3/128, BATCH/128), 256, SMEM_G>>>(
                xl_h, HID, 0,
                wih_h + (size_t)l * H3 * HID, HID, 0,
                gbih + (size_t)l * H3, 0,
                gi, H3, 0, HID);
        }
        gru_gate<<<(int)(BH/4/256), 256>>>(
            gi, gh + (size_t)l * BH3, hidden + (size_t)l * BH,
            out_hidden + (size_t)l * BH, xl_h, dec_h, (l == NLAY-1) ? 1 : 0);
    }

    // ---- RVQ cascade ----
    for (int q = 0; q < NQ; q++) {
        hgemm<float><<<dim3(KCB/128, BATCH/128), 256, SMEM_G>>>(
            dec_h, DECK, 0,
            dw_h + (size_t)q * KCB * DECK, DECK, 0,
            dec_b + (size_t)q * KCB, 0,
            out_logits + (size_t)q * BK, KCB, 0, DECK);
        rvq_fused<<<BATCH/32, 256, SMEM_R>>>(
            out_logits + (size_t)q * BK, ET_h + (size_t)q * D_IN * KCB,
            cum, dec_h, out_step, q);
    }
}

// round 17
// speedup vs baseline: 1.0583x; 1.0098x over previous
#include <cuda_runtime.h>
#include <cuda_fp16.h>
#include <math.h>
#include <stdint.h>

// ---------------- problem constants ----------------
#define BATCH   8192
#define D_IN    128
#define D_COND  3
#define HID     1024
#define NLAY    4
#define NQ      8
#define KCB     1024
#define H3      (3*HID)        // 3072
#define DECK    (HID + D_IN)   // 1152
#define LPN     512
#define DPAD    192            // padded K for fused layer-0 input GEMM
#define INV_TAU (1.0f/0.6f)

// ---------------- scratch (no allocation allowed) ----------------
__device__ float  g_cum  [(size_t)BATCH * D_IN];
__device__ float  g_beff [H3];                        // fused layer-0 bias
__device__ float  g_zerof[1024];                      // stays 0 (never written)
// fp16 buffers
__device__ __half g_gi   [(size_t)BATCH * H3];
__device__ __half g_gh   [(size_t)NLAY * BATCH * H3];
__device__ __half g_xl_h [(size_t)BATCH * HID];
__device__ __half g_hid_h[(size_t)NLAY * BATCH * HID];
__device__ __half g_wih_h[(size_t)NLAY * H3 * HID];
__device__ __half g_whh_h[(size_t)NLAY * H3 * HID];
__device__ __half g_dw_h [(size_t)NQ * KCB * DECK];
__device__ __half g_ET_h [(size_t)NQ * D_IN * KCB];
__device__ __half g_Wfull[(size_t)H3 * DPAD];         // fused layer-0 weight (cols 131..191 stay 0)
__device__ __half g_latwT[(size_t)D_IN * LPN];        // lat_w transposed fp16
__device__ __half g_xpad [(size_t)BATCH * DPAD];      // padded fp16 x

// =====================================================================
__device__ __forceinline__ uint32_t smem_u32(const void* p) {
    uint32_t a;
    asm("{ .reg .u64 t; cvta.to.shared.u64 t, %1; cvt.u32.u64 %0, t; }" : "=r"(a) : "l"(p));
    return a;
}
#define CP_ASYNC16(dst, src) \
    asm volatile("cp.async.cg.shared.global [%0], [%1], 16;" :: "r"(dst), "l"(src) : "memory")
#define CP_COMMIT() asm volatile("cp.async.commit_group;" ::: "memory")
template <int N> __device__ __forceinline__ void cp_wait() {
    asm volatile("cp.async.wait_group %0;" :: "n"(N) : "memory");
}
#define LDSM_X4(r, addr) \
    asm volatile("ldmatrix.sync.aligned.m8n8.x4.shared.b16 {%0,%1,%2,%3}, [%4];" \
        : "=r"((r)[0]), "=r"((r)[1]), "=r"((r)[2]), "=r"((r)[3]) : "r"(addr))
#define LDSM_X2(r, addr) \
    asm volatile("ldmatrix.sync.aligned.m8n8.x2.shared.b16 {%0,%1}, [%2];" \
        : "=r"((r)[0]), "=r"((r)[1]) : "r"(addr))

__device__ __forceinline__ void mma_f16(float* c, const uint32_t* a, const uint32_t* b) {
    asm volatile(
        "mma.sync.aligned.m16n8k16.row.col.f32.f16.f16.f32 "
        "{%0,%1,%2,%3}, {%4,%5,%6,%7}, {%8,%9}, {%0,%1,%2,%3};"
        : "+f"(c[0]), "+f"(c[1]), "+f"(c[2]), "+f"(c[3])
        : "r"(a[0]), "r"(a[1]), "r"(a[2]), "r"(a[3]), "r"(b[0]), "r"(b[1]));
}

// =====================================================================
// fp16 mma.sync GEMM (z-batched): C[M,N] = A[M,K] @ W[N,K]^T + bias[N]
//   BM=BN=128, BK=64, 256 threads (8 warps: 2m x 4n), warp tile 64x32.
//   3-stage cp.async pipeline; EVERY iteration commits a group (empty in
//   the tail) so wait_group<1> at iteration kt proves stage kt landed.
//   OutT = float or __half. Requires K%64==0, nK>=2, M%128==0, N%128==0.
// =====================================================================
#define SPH 72                              // halves per smem row (64 + 8 pad)

template <typename OutT>
__global__ void __launch_bounds__(256, 2)
hgemm(const __half* __restrict__ A, int lda, size_t zsA,
      const __half* __restrict__ W, int ldw, size_t zsW,
      const float* __restrict__ bias, size_t zsB,
      OutT* __restrict__ C, int ldc, size_t zsC, int K)
{
    constexpr int ASTG = 128 * SPH;
    constexpr int STG  = 2 * ASTG;

    extern __shared__ __half smh[];         // [3][STG]

    A    += (size_t)blockIdx.z * zsA;
    W    += (size_t)blockIdx.z * zsW;
    bias += (size_t)blockIdx.z * zsB;
    C    += (size_t)blockIdx.z * zsC;

    const int tid = threadIdx.x, lane = tid & 31, wid = tid >> 5;
    const int bm = blockIdx.y * 128, bn = blockIdx.x * 128;
    const int wm = (wid >> 2) * 64, wn = (wid & 3) * 32;
    const uint32_t sBase = smem_u32(smh);

    float acc[4][4][4];
#pragma unroll
    for (int i = 0; i < 4; i++)
#pragma unroll
        for (int j = 0; j < 4; j++)
#pragma unroll
            for (int k = 0; k < 4; k++) acc[i][j][k] = 0.f;

    const int nK = K / 64;

    auto prefetch = [&](int kt) {
        const int s = kt % 3;
#pragma unroll
        for (int i = 0; i < 4; i++) {
            int c = tid + i * 256;
            int row = c >> 3, q = c & 7;
            uint32_t dst = sBase + (s * STG + row * SPH) * 2 + q * 16;
            CP_ASYNC16(dst, A + (size_t)(bm + row) * lda + kt * 64 + q * 8);
        }
#pragma unroll
        for (int i = 0; i < 4; i++) {
            int c = tid + i * 256;
            int row = c >> 3, q = c & 7;
            uint32_t dst = sBase + (s * STG + ASTG + row * SPH) * 2 + q * 16;
            CP_ASYNC16(dst, W + (size_t)(bn + row) * ldw + kt * 64 + q * 8);
        }
        CP_COMMIT();
    };

    prefetch(0); prefetch(1);               // nK >= 2 at all call sites

    for (int kt = 0; kt < nK; kt++) {
        cp_wait<1>();                        // stage kt landed (invariant)
        __syncthreads();                     // stage (kt-1) reads done
        if (kt + 2 < nK) prefetch(kt + 2);
        else CP_COMMIT();                    // one-commit-per-iter invariant

        const uint32_t base = sBase + (kt % 3) * STG * 2;
#pragma unroll
        for (int g = 0; g < 4; g++) {        // four k16 groups per k-tile
            uint32_t a[4][4], b[4][2];
#pragma unroll
            for (int mt = 0; mt < 4; mt++) {
                int r = wm + mt * 16 + (lane & 15);
                uint32_t ad = base + (r * SPH + g * 16 + ((lane >> 4) << 3)) * 2;
                LDSM_X4(a[mt], ad);
            }
#pragma unroll
            for (int nt = 0; nt < 4; nt++) {
                int r = wn + nt * 8 + (lane & 7);
                uint32_t ad = base + (ASTG + r * SPH + g * 16 + (((lane >> 3) & 1) << 3)) * 2;
                LDSM_X2(b[nt], ad);
            }
#pragma unroll
            for (int mt = 0; mt < 4; mt++)
#pragma unroll
                for (int nt = 0; nt < 4; nt++)
                    mma_f16(acc[mt][nt], a[mt], b[nt]);
        }
    }

    // ---- epilogue ----
#pragma unroll
    for (int mt = 0; mt < 4; mt++) {
        const int r0 = bm + wm + mt * 16 + (lane >> 2);
#pragma unroll
        for (int nt = 0; nt < 4; nt++) {
            const int c0 = bn + wn + nt * 8 + (lane & 3) * 2;
            const float b0 = bias[c0], b1 = bias[c0 + 1];
            if constexpr (sizeof(OutT) == 4) {
                float2 v0 = make_float2(acc[mt][nt][0] + b0, acc[mt][nt][1] + b1);
                float2 v1 = make_float2(acc[mt][nt][2] + b0, acc[mt][nt][3] + b1);
                *(float2*)((float*)C + (size_t)r0 * ldc + c0) = v0;
                *(float2*)((float*)C + (size_t)(r0 + 8) * ldc + c0) = v1;
            } else {
                __half2 v0 = __floats2half2_rn(acc[mt][nt][0] + b0, acc[mt][nt][1] + b1);
                __half2 v1 = __floats2half2_rn(acc[mt][nt][2] + b0, acc[mt][nt][3] + b1);
                *(__half2*)((__half*)C + (size_t)r0 * ldc + c0) = v0;
                *(__half2*)((__half*)C + (size_t)(r0 + 8) * ldc + c0) = v1;
            }
        }
    }
}

// =====================================================================
// Fused RVQ tail:
//   softmax(logits_q/tau) -> fp16 w (smem) -> e = w @ ET^T (mma)
//   -> step += e ; cum += e ; cum fp16 -> smem
//   -> logits_{q+1} += cum @ dw_c[q+1]^T   (K=128 tail of decoder, fused)
// One CTA = 32 batch rows, 256 threads, 2-stage cp.async streams
// (E in e-phase, dw_c chunks in tail phase). 102.9KB smem -> 2 CTAs/SM.
// =====================================================================
#define WROW 1032                            // w smem row stride (halves)
#define ESTG (128 * SPH)                     // E halves per stage
#define CROW 136                             // cum / B row stride (halves)
#define BSTG (64 * CROW)                     // B chunk halves per stage

__global__ void __launch_bounds__(256, 2)
rvq_fused(const float* __restrict__ logits,      // (BATCH,KCB) for q
          const __half* __restrict__ ET,          // (D_IN,KCB) for q
          float* __restrict__ cum,
          float* __restrict__ step_out,
          float* __restrict__ logits_next,        // (BATCH,KCB) for q+1 (q<NQ-1)
          const __half* __restrict__ dwc_next,    // dw rows of q+1, tail cols (ld=DECK)
          int q)
{
    extern __shared__ __half smh[];          // w/cum: 32*WROW ; E/B: 2*ESTG
    __half* wsm = smh;
    __half* esm = smh + 32 * WROW;

    const int tid = threadIdx.x, lane = tid & 31, wid = tid >> 5;
    const size_t rowBase = (size_t)blockIdx.x * 32;
    const uint32_t wB = smem_u32(wsm);
    const uint32_t eB = smem_u32(esm);

    auto prefE = [&](int kc) {
        const int s = kc & 1;
#pragma unroll
        for (int i = 0; i < 4; i++) {
            int c = tid + i * 256;
            int row = c >> 3, qk = c & 7;
            uint32_t dst = eB + (s * ESTG + row * SPH) * 2 + qk * 16;
            CP_ASYNC16(dst, ET + (size_t)row * KCB + kc * 64 + qk * 8);
        }
        CP_COMMIT();
    };
    prefE(0);

    // ---- softmax phase: warp handles rows wid*4 .. wid*4+3 ----
#pragma unroll
    for (int rr = 0; rr < 4; rr++) {
        const int row = wid * 4 + rr;
        const float* lr = logits + (rowBase + row) * KCB;
        float v[32];
        float m = -INFINITY;
#pragma unroll
        for (int i = 0; i < 32; i++) { v[i] = lr[lane + 32*i]; m = fmaxf(m, v[i]); }
#pragma unroll
        for (int o = 16; o; o >>= 1) m = fmaxf(m, __shfl_xor_sync(0xffffffffu, m, o));
        float s = 0.f;
#pragma unroll
        for (int i = 0; i < 32; i++) { v[i] = expf((v[i] - m) * INV_TAU); s += v[i]; }
#pragma unroll
        for (int o = 16; o; o >>= 1) s += __shfl_xor_sync(0xffffffffu, s, o);
        float inv = 1.f / s;
#pragma unroll
        for (int i = 0; i < 32; i++)
            wsm[row * WROW + lane + 32*i] = __float2half_rn(v[i] * inv);
    }

    // ---- e-mma phase: e[32,128] = w[32,1024] @ ET[128,1024]^T ----
    const int wm = (wid >> 2) * 16, wn = (wid & 3) * 32;
    float acc[4][4];
#pragma unroll
    for (int j = 0; j < 4; j++)
#pragma unroll
        for (int k = 0; k < 4; k++) acc[j][k] = 0.f;

    for (int kc = 0; kc < KCB / 64; kc++) {
        cp_wait<0>();                         // stage kc fully landed
        __syncthreads();                      // stage (kc-1) reads done; softmax writes (kc==0)
        if (kc + 1 < KCB / 64) prefE(kc + 1);

        const uint32_t ebase = eB + (kc & 1) * ESTG * 2;
#pragma unroll
        for (int g = 0; g < 4; g++) {
            uint32_t a[4], b[4][2];
            {
                int r = wm + (lane & 15);
                uint32_t ad = wB + (r * WROW + kc * 64 + g * 16 + ((lane >> 4) << 3)) * 2;
                LDSM_X4(a, ad);
            }
#pragma unroll
            for (int nt = 0; nt < 4; nt++) {
                int r = wn + nt * 8 + (lane & 7);
                uint32_t ad = ebase + (r * SPH + g * 16 + (((lane >> 3) & 1) << 3)) * 2;
                LDSM_X2(b[nt], ad);
            }
#pragma unroll
            for (int nt = 0; nt < 4; nt++)
                mma_f16(acc[nt], a, b[nt]);
        }
    }

    // ---- update epilogue: step/cum; cum fp16 into smem (w region, now dead) ----
    __syncthreads();                          // all e-phase w reads done before overwrite
    const int r0 = wm + (lane >> 2);
#pragma unroll
    for (int nt = 0; nt < 4; nt++) {
        const int c0 = wn + nt * 8 + (lane & 3) * 2;
#pragma unroll
        for (int half = 0; half < 2; half++) {
            const int r = r0 + half * 8;
            const size_t b = rowBase + r;
            float cv2[2];
#pragma unroll
            for (int cc = 0; cc < 2; cc++) {
                const int c = c0 + cc;
                const float eV = acc[nt][half * 2 + cc];
                const size_t idx = b * D_IN + c;
                float sp = (q == 0) ? 0.f : step_out[idx];
                step_out[idx] = sp + eV;
                float cv = (q == 0) ? 0.f : cum[idx];
                cv += eV;
                cv2[cc] = cv;
                if (q < NQ - 1) cum[idx] = cv;
            }
            if (q < NQ - 1)
                *(__half2*)(wsm + r * CROW + c0) = __floats2half2_rn(cv2[0], cv2[1]);
        }
    }

    // ---- fused decoder tail: logits_next += cum[32,128] @ dwc_next[1024,128]^T ----
    if (q < NQ - 1) {
        __syncthreads();                      // cum smem visible to all

        auto prefB = [&](int nc) {
            const int s = nc & 1;
#pragma unroll
            for (int i = 0; i < 4; i++) {
                int c = tid + i * 256;        // 64 rows x 16 chunks of 16B
                int row = c >> 4, qk = c & 15;
                uint32_t dst = eB + (s * BSTG + row * CROW) * 2 + qk * 16;
                CP_ASYNC16(dst, dwc_next + (size_t)(nc * 64 + row) * DECK + qk * 8);
            }
            CP_COMMIT();
        };
        prefB(0);

        const int wmT = (wid >> 2) * 16, wnT = (wid & 3) * 16;
        uint32_t a[8][4];                     // cum a-frags, hoisted over all chunks
#pragma unroll
        for (int g = 0; g < 8; g++) {
            int r = wmT + (lane & 15);
            LDSM_X4(a[g], wB + (r * CROW + g * 16 + ((lane >> 4) << 3)) * 2);
        }

        for (int nc = 0; nc < 16; nc++) {
            cp_wait<0>();
            __syncthreads();
            if (nc + 1 < 16) prefB(nc + 1);

            const uint32_t bbase = eB + ((nc & 1) * BSTG) * 2;
            float acc2[2][4];
#pragma unroll
            for (int nt = 0; nt < 2; nt++)
#pragma unroll
                for (int k = 0; k < 4; k++) acc2[nt][k] = 0.f;
#pragma unroll
            for (int g = 0; g < 8; g++) {
                uint32_t b[2][2];
#pragma unroll
                for (int nt = 0; nt < 2; nt++) {
                    int r = wnT + nt * 8 + (lane & 7);
                    uint32_t ad = bbase + (r * CROW + g * 16 + (((lane >> 3) & 1) << 3)) * 2;
                    LDSM_X2(b[nt], ad);
                }
#pragma unroll
                for (int nt = 0; nt < 2; nt++)
                    mma_f16(acc2[nt], a[g], b[nt]);
            }
            // RMW logits_next (each CTA owns disjoint rows)
            const size_t rA = rowBase + wmT + (lane >> 2);
#pragma unroll
            for (int nt = 0; nt < 2; nt++) {
                const int col = nc * 64 + wnT + nt * 8 + (lane & 3) * 2;
                float* p0 = logits_next + rA * KCB + col;
                float* p1 = logits_next + (rA + 8) * KCB + col;
                float2 o0 = *(float2*)p0;
                o0.x += acc2[nt][0]; o0.y += acc2[nt][1];
                *(float2*)p0 = o0;
                float2 o1 = *(float2*)p1;
                o1.x += acc2[nt][2]; o1.y += acc2[nt][3];
                *(float2*)p1 = o1;
            }
        }
    }
}

// =====================================================================
// merged fp32 -> fp16 convert of all four operand blocks (one launch)
// =====================================================================
#define CVN_W  ((size_t)NLAY * H3 * HID / 4)     // wih (== whh)
#define CVN_D  ((size_t)NQ * KCB * DECK / 4)     // dec_w
#define CVN_H  ((size_t)NLAY * BATCH * HID / 4)  // hidden
#define CVN_TOT (2 * CVN_W + CVN_D + CVN_H)

__device__ __forceinline__ void cv4(const float4* s, uint2* d, size_t i) {
    float4 v = s[i];
    __half2 h01 = __floats2half2_rn(v.x, v.y);
    __half2 h23 = __floats2half2_rn(v.z, v.w);
    uint2 u; u.x = *(uint32_t*)&h01; u.y = *(uint32_t*)&h23;
    d[i] = u;
}

__global__ void conv_all(const float4* __restrict__ wih, uint2* __restrict__ wih_h,
                         const float4* __restrict__ whh, uint2* __restrict__ whh_h,
                         const float4* __restrict__ dw,  uint2* __restrict__ dw_h,
                         const float4* __restrict__ hid, uint2* __restrict__ hid_h)
{
    size_t i = (size_t)blockIdx.x * blockDim.x + threadIdx.x;
    if (i < CVN_W)                     { cv4(wih, wih_h, i); return; }
    i -= CVN_W;
    if (i < CVN_W)                     { cv4(whh, whh_h, i); return; }
    i -= CVN_W;
    if (i < CVN_D)                     { cv4(dw, dw_h, i); return; }
    i -= CVN_D;
    if (i < CVN_H)                     { cv4(hid, hid_h, i); }
}

// =====================================================================
// lat_w (LPN=512, D_IN=128) fp32 -> latwT (D_IN=128, LPN=512) fp16
// =====================================================================
__global__ void transpose_latw(const float* __restrict__ lat_w, __half* __restrict__ latwT)
{
    __shared__ float t[32][33];
    int n0 = blockIdx.x * 32, d0 = blockIdx.y * 32;
#pragma unroll
    for (int i = 0; i < 32; i += 8)
        t[threadIdx.y + i][threadIdx.x] =
            lat_w[(size_t)(n0 + threadIdx.y + i) * D_IN + d0 + threadIdx.x];
    __syncthreads();
#pragma unroll
    for (int i = 0; i < 32; i += 8)
        latwT[(size_t)(d0 + threadIdx.y + i) * LPN + n0 + threadIdx.x] =
            __float2half_rn(t[threadIdx.x][threadIdx.y + i]);
}

// =====================================================================
// cond-part of fused layer-0 weight + effective bias (float4-vectorized).
// One warp per output row j (H3 rows).
// =====================================================================
__global__ void fuse_cond_bias(const float* __restrict__ gwih0,
                               const float* __restrict__ cond_w,
                               const float* __restrict__ lat_b,
                               const float* __restrict__ cond_b,
                               const float* __restrict__ gbih0,
                               __half* __restrict__ Wfull,
                               float* __restrict__ b_eff)
{
    int gw = (blockIdx.x * blockDim.x + threadIdx.x) >> 5;   // row j
    int lane = threadIdx.x & 31;
    const float4* wr = (const float4*)(gwih0 + (size_t)gw * HID);
    float c0 = 0.f, c1 = 0.f, c2 = 0.f, bl = 0.f, bc = 0.f;
#pragma unroll
    for (int i = lane; i < 128; i += 32) {
        float4 wl = wr[i];
        float4 lb = ((const float4*)lat_b)[i];
        bl += wl.x*lb.x + wl.y*lb.y + wl.z*lb.z + wl.w*lb.w;
        float4 wc = wr[128 + i];
        float4 cb = ((const float4*)cond_b)[i];
        bc += wc.x*cb.x + wc.y*cb.y + wc.z*cb.z + wc.w*cb.w;
        const float* cw = cond_w + 12 * i;   // cond_w rows 4i..4i+3
        c0 += wc.x*cw[0] + wc.y*cw[3] + wc.z*cw[6] + wc.w*cw[9];
        c1 += wc.x*cw[1] + wc.y*cw[4] + wc.z*cw[7] + wc.w*cw[10];
        c2 += wc.x*cw[2] + wc.y*cw[5] + wc.z*cw[8] + wc.w*cw[11];
    }
#pragma unroll
    for (int o = 16; o; o >>= 1) {
        c0 += __shfl_xor_sync(0xffffffffu, c0, o);
        c1 += __shfl_xor_sync(0xffffffffu, c1, o);
        c2 += __shfl_xor_sync(0xffffffffu, c2, o);
        bl += __shfl_xor_sync(0xffffffffu, bl, o);
        bc += __shfl_xor_sync(0xffffffffu, bc, o);
    }
    if (lane == 0) {
        __half* wf = Wfull + (size_t)gw * DPAD;
        wf[128] = __float2half_rn(c0);
        wf[129] = __float2half_rn(c1);
        wf[130] = __float2half_rn(c2);
        b_eff[gw] = gbih0[gw] + bl + bc;
    }
}

// pad x (B x 131 fp32, unaligned) -> xpad (B x 192 fp16, zero tail)
__global__ void pad_x(const float* __restrict__ x, __half* __restrict__ xpad)
{
    int idx = blockIdx.x * blockDim.x + threadIdx.x;   // BATCH * DPAD
    int b = idx / DPAD, c = idx - b * DPAD;
    float v = (c < D_IN + D_COND) ? x[(size_t)b * (D_IN + D_COND) + c] : 0.f;
    xpad[(size_t)b * DPAD + c] = __float2half_rn(v);
}

__device__ __forceinline__ float sigm(float v) { return 1.f / (1.f + expf(-v)); }

// GRU gates from fp16 gi/gh; fp32 h to output, fp16 h to next-layer operand.
__global__ void gru_gate(const __half* __restrict__ gi,
                         const __half* __restrict__ gh,
                         const float* __restrict__ hprev,
                         float* __restrict__ hout,
                         __half* __restrict__ xl_h)
{
    int idx = blockIdx.x * blockDim.x + threadIdx.x;   // BATCH * 256
    int b = idx >> 8, j4 = idx & 255;
    const __half2* gib = (const __half2*)(gi + (size_t)b * H3);
    const __half2* ghb = (const __half2*)(gh + (size_t)b * H3);
    float2 ir0 = __half22float2(gib[j4*2]),        ir1 = __half22float2(gib[j4*2+1]);
    float2 iz0 = __half22float2(gib[512 + j4*2]),  iz1 = __half22float2(gib[512 + j4*2+1]);
    float2 in0 = __half22float2(gib[1024 + j4*2]), in1 = __half22float2(gib[1024 + j4*2+1]);
    float2 hr0 = __half22float2(ghb[j4*2]),        hr1 = __half22float2(ghb[j4*2+1]);
    float2 hz0 = __half22float2(ghb[512 + j4*2]),  hz1 = __half22float2(ghb[512 + j4*2+1]);
    float2 hn0 = __half22float2(ghb[1024 + j4*2]), hn1 = __half22float2(ghb[1024 + j4*2+1]);
    float4 hp = ((const float4*)hprev)[idx];
    float4 h;
    {
        float r = sigm(ir0.x + hr0.x), z = sigm(iz0.x + hz0.x);
        float n = tanhf(in0.x + r * hn0.x); h.x = (1.f - z) * n + z * hp.x;
    }{
        float r = sigm(ir0.y + hr0.y), z = sigm(iz0.y + hz0.y);
        float n = tanhf(in0.y + r * hn0.y); h.y = (1.f - z) * n + z * hp.y;
    }{
        float r = sigm(ir1.x + hr1.x), z = sigm(iz1.x + hz1.x);
        float n = tanhf(in1.x + r * hn1.x); h.z = (1.f - z) * n + z * hp.z;
    }{
        float r = sigm(ir1.y + hr1.y), z = sigm(iz1.y + hz1.y);
        float n = tanhf(in1.y + r * hn1.y); h.w = (1.f - z) * n + z * hp.w;
    }
    ((float4*)hout)[idx] = h;
    __half2 h01 = __floats2half2_rn(h.x, h.y);
    __half2 h23 = __floats2half2_rn(h.z, h.w);
    uint2 u; u.x = *(uint32_t*)&h01; u.y = *(uint32_t*)&h23;
    ((uint2*)xl_h)[idx] = u;
}

// E (NQ,K,D_IN) -> ET_h (NQ,D_IN,K) fp16
__global__ void transposeE(const float* __restrict__ E, __half* __restrict__ ET)
{
    __shared__ float t[32][33];
    int q = blockIdx.z;
    int k0 = blockIdx.x * 32, n0 = blockIdx.y * 32;
    const float* Eq = E + (size_t)q * KCB * D_IN;
    __half* Tq = ET + (size_t)q * D_IN * KCB;
#pragma unroll
    for (int i = 0; i < 32; i += 8)
        t[threadIdx.y + i][threadIdx.x] =
            Eq[(size_t)(k0 + threadIdx.y + i) * D_IN + n0 + threadIdx.x];
    __syncthreads();
#pragma unroll
    for (int i = 0; i < 32; i += 8)
        Tq[(size_t)(n0 + threadIdx.y + i) * KCB + k0 + threadIdx.x] =
            __float2half_rn(t[threadIdx.x][threadIdx.y + i]);
}

// =====================================================================
extern "C" void kernel_launch(void* const* d_in, const int* in_sizes, int n_in,
                              void* d_out, int out_size)
{
    const float* x      = (const float*)d_in[0];
    const float* hidden = (const float*)d_in[1];
    const float* lat_w  = (const float*)d_in[2];
    const float* lat_b  = (const float*)d_in[3];
    const float* cond_w = (const float*)d_in[4];
    const float* cond_b = (const float*)d_in[5];
    const float* gwih   = (const float*)d_in[6];
    const float* gwhh   = (const float*)d_in[7];
    const float* gbih   = (const float*)d_in[8];
    const float* gbhh   = (const float*)d_in[9];
    const float* dec_w  = (const float*)d_in[10];
    const float* dec_b  = (const float*)d_in[11];
    const float* E_eff  = (const float*)d_in[12];

    const size_t BH  = (size_t)BATCH * HID;
    const size_t BH3 = (size_t)BATCH * H3;
    const size_t BK  = (size_t)BATCH * KCB;

    float* out_logits = (float*)d_out;
    float* out_hidden = out_logits + (size_t)NQ * BK;
    float* out_step   = out_hidden + (size_t)NLAY * BH;

    float *cum, *beff, *zerof;
    __half *gi, *gh, *xl_h, *hid_h, *wih_h, *whh_h, *dw_h, *ET_h;
    __half *Wfull, *latwT, *xpad;
    cudaGetSymbolAddress((void**)&cum,   g_cum);
    cudaGetSymbolAddress((void**)&beff,  g_beff);
    cudaGetSymbolAddress((void**)&zerof, g_zerof);
    cudaGetSymbolAddress((void**)&gi,    g_gi);
    cudaGetSymbolAddress((void**)&gh,    g_gh);
    cudaGetSymbolAddress((void**)&xl_h,  g_xl_h);
    cudaGetSymbolAddress((void**)&hid_h, g_hid_h);
    cudaGetSymbolAddress((void**)&wih_h, g_wih_h);
    cudaGetSymbolAddress((void**)&whh_h, g_whh_h);
    cudaGetSymbolAddress((void**)&dw_h,  g_dw_h);
    cudaGetSymbolAddress((void**)&ET_h,  g_ET_h);
    cudaGetSymbolAddress((void**)&Wfull, g_Wfull);
    cudaGetSymbolAddress((void**)&latwT, g_latwT);
    cudaGetSymbolAddress((void**)&xpad,  g_xpad);

    const int SMEM_G = 3 * 2 * 128 * SPH * 2;            // 110592 B
    const int SMEM_R = (32 * WROW + 2 * 128 * SPH) * 2;  // 102912 B
    cudaFuncSetAttribute(hgemm<float>,  cudaFuncAttributeMaxDynamicSharedMemorySize, SMEM_G);
    cudaFuncSetAttribute(hgemm<__half>, cudaFuncAttributeMaxDynamicSharedMemorySize, SMEM_G);
    cudaFuncSetAttribute(rvq_fused, cudaFuncAttributeMaxDynamicSharedMemorySize, SMEM_R);

    // ---- operand pre-conversion: ONE launch ----
    conv_all<<<(int)((CVN_TOT + 255) / 256), 256>>>(
        (const float4*)gwih, (uint2*)wih_h,
        (const float4*)gwhh, (uint2*)whh_h,
        (const float4*)dec_w, (uint2*)dw_h,
        (const float4*)hidden, (uint2*)hid_h);

    // ---- fused layer-0 input weights ----
    transpose_latw<<<dim3(LPN/32, D_IN/32), dim3(32, 8)>>>(lat_w, latwT);
    hgemm<__half><<<dim3(1, H3/128), 256, SMEM_G>>>(
        wih_h, HID, 0,
        latwT, LPN, 0,
        zerof, 0,
        Wfull, DPAD, 0, LPN);
    fuse_cond_bias<<<H3/8, 256>>>(gwih, cond_w, lat_b, cond_b, gbih, Wfull, beff);
    pad_x<<<(BATCH*DPAD)/256, 256>>>(x, xpad);

    // ---- E transpose -> fp16 ----
    transposeE<<<dim3(KCB/32, D_IN/32, NQ), dim3(32, 8)>>>(E_eff, ET_h);

    // ---- all 4 gh GEMMs in ONE z-batched launch ----
    hgemm<__half><<<dim3(H3/128, BATCH/128, NLAY), 256, SMEM_G>>>(
        hid_h, HID, BH,
        whh_h, HID, (size_t)H3 * HID,
        gbhh, H3,
        gh, H3, BH3, HID);

    // ---- 4-layer GRU chain ----
    for (int l = 0; l < NLAY; l++) {
        if (l == 0) {
            hgemm<__half><<<dim3(H3/128, BATCH/128), 256, SMEM_G>>>(
                xpad, DPAD, 0,
                Wfull, DPAD, 0,
                beff, 0,
                gi, H3, 0, DPAD);
        } else {
            hgemm<__half><<<dim3(H3/128, BATCH/128), 256, SMEM_G>>>(
                xl_h, HID, 0,
                wih_h + (size_t)l * H3 * HID, HID, 0,
                gbih + (size_t)l * H3, 0,
                gi, H3, 0, HID);
        }
        gru_gate<<<(int)(BH/4/256), 256>>>(
            gi, gh + (size_t)l * BH3, hidden + (size_t)l * BH,
            out_hidden + (size_t)l * BH, xl_h);
    }

    // ---- decoder heads: all 8 q's in ONE z-batched GEMM (K=1024, h part) ----
    hgemm<float><<<dim3(KCB/128, BATCH/128, NQ), 256, SMEM_G>>>(
        xl_h, HID, 0,
        dw_h, DECK, (size_t)KCB * DECK,
        dec_b, KCB,
        out_logits, KCB, BK, HID);

    // ---- RVQ cascade: fused softmax + e + update + decoder K=128 tail for q+1 ----
    for (int q = 0; q < NQ; q++) {
        rvq_fused<<<BATCH/32, 256, SMEM_R>>>(
            out_logits + (size_t)q * BK, ET_h + (size_t)q * D_IN * KCB,
            cum, out_step,
            out_logits + (size_t)(q + 1 < NQ ? q + 1 : q) * BK,
            dw_h + (size_t)(q + 1 < NQ ? q + 1 : q) * KCB * DECK + HID,
            q);
    }
}